// round 5
// baseline (speedup 1.0000x reference)
#include <cuda_runtime.h>
#include <cuda_bf16.h>
#include <math.h>

// Problem constants (fixed shapes per reference)
#define NN 100000
#define EE 1600000
#define DD 64
#define GG 64

// ---------------- scratch (static device memory; no allocations) -------------
__device__ __align__(16) float g_bufA[NN * DD];  // gemm output, pre-scaled by dinv[src]
__device__ __align__(16) float g_bufB[NN * DD];  // layer output h (relu'd)
__device__ int   g_src[EE];
__device__ int   g_dst[EE];
__device__ int   g_bat[NN];
__device__ int   g_deg[NN];            // in-degree (excl. self loop)
__device__ int   g_tmpscan[NN];        // block-local exclusive scan
__device__ int   g_rowptr[NN + 1];
__device__ int   g_cursor[NN];
__device__ int   g_colidx[EE];
__device__ float g_dinv[NN];
__device__ int   g_partial[256];
__device__ int   g_blockoff[256];
__device__ float g_pooled[GG * DD];
__device__ int   g_is64;

// ---------------- helpers ----------------------------------------------------
__device__ __forceinline__ int lower_bound_i(const int* a, int n, int v) {
    int lo = 0, hi = n;
    while (lo < hi) {
        int m = (lo + hi) >> 1;
        if (a[m] < v) lo = m + 1; else hi = m;
    }
    return lo;
}

// ---------------- kernels ----------------------------------------------------

// Detect index dtype. For int64 little-endian data with values < 2^32, every odd
// int32 slot is 0. For int32 data the odd slots are node ids (random, nonzero).
__global__ void k_detect(const void* __restrict__ ei_raw, int e) {
    const int* p = (const int*)ei_raw;
    int t = threadIdx.x;
    int nz = 0;
    int limit = min(512, e);            // check odd slots of first 512 int32 pairs
    for (int i = t; i < limit; i += 256) {
        if (p[2 * i + 1] != 0) nz = 1;
    }
    __shared__ int anynz;
    if (t == 0) anynz = 0;
    __syncthreads();
    if (nz) atomicOr(&anynz, 1);
    __syncthreads();
    if (t == 0) g_is64 = anynz ? 0 : 1;
}

// zero deg + pooled
__global__ void k_zero(int n) {
    int i = blockIdx.x * blockDim.x + threadIdx.x;
    if (i < n) g_deg[i] = 0;
    if (i < GG * DD) g_pooled[i] = 0.f;
}

// convert edge_index to int32 src/dst + histogram of dst
__global__ void k_convert_edges(const void* __restrict__ ei_raw, int e) {
    int i = blockIdx.x * blockDim.x + threadIdx.x;
    if (i >= e) return;
    int s, d;
    if (g_is64) {
        const long long* p = (const long long*)ei_raw;
        s = (int)p[i];
        d = (int)p[(size_t)e + i];
    } else {
        const int* p = (const int*)ei_raw;
        s = p[i];
        d = p[e + i];
    }
    g_src[i] = s;
    g_dst[i] = d;
    atomicAdd(&g_deg[d], 1);
}

// convert batch ids to int32
__global__ void k_convert_batch(const void* __restrict__ bat_raw, int n) {
    int i = blockIdx.x * blockDim.x + threadIdx.x;
    if (i >= n) return;
    int v;
    if (g_is64) v = (int)((const long long*)bat_raw)[i];
    else        v = ((const int*)bat_raw)[i];
    g_bat[i] = v;
}

// block-level scan (1024/block)
__global__ void k_scan1(int n) {
    __shared__ int sh[1024];
    int t = threadIdx.x;
    int i = blockIdx.x * 1024 + t;
    int v = (i < n) ? g_deg[i] : 0;
    sh[t] = v;
    __syncthreads();
    for (int off = 1; off < 1024; off <<= 1) {
        int x = (t >= off) ? sh[t - off] : 0;
        __syncthreads();
        sh[t] += x;
        __syncthreads();
    }
    int incl = sh[t];
    if (i < n) g_tmpscan[i] = incl - v;
    if (t == 1023) g_partial[blockIdx.x] = incl;
}

// scan block partials (nb <= 128)
__global__ void k_scan2(int nb) {
    __shared__ int sh[128];
    int t = threadIdx.x;
    sh[t] = (t < nb) ? g_partial[t] : 0;
    __syncthreads();
    if (t == 0) {
        int run = 0;
        for (int b = 0; b < nb; b++) { int x = sh[b]; sh[b] = run; run += x; }
    }
    __syncthreads();
    if (t < nb) g_blockoff[t] = sh[t];
}

// finalize rowptr, cursor, dinv
__global__ void k_scan3(int n, int e) {
    int i = blockIdx.x * blockDim.x + threadIdx.x;
    if (i < n) {
        int rp = g_tmpscan[i] + g_blockoff[i >> 10];
        g_rowptr[i] = rp;
        g_cursor[i] = rp;
        g_dinv[i] = rsqrtf((float)g_deg[i] + 1.0f);  // +1 = self loop
        if (i == 0) g_rowptr[n] = e;
    }
}

// scatter src ids into CSR
__global__ void k_fill(int e) {
    int i = blockIdx.x * blockDim.x + threadIdx.x;
    if (i < e) {
        int s = g_src[i];
        int d = g_dst[i];
        int pos = atomicAdd(&g_cursor[d], 1);
        g_colidx[pos] = s;
    }
}

// g_bufA[row] = (in[row] @ W) * dinv[row]    (W: 64x64 row-major)
// in = xparam (layer 1, harness pointer) or g_bufB (layer 2) when xparam==null.
// block = 256 threads (8 warps), each warp does 8 rows -> 64 rows/block
__global__ __launch_bounds__(256) void k_gemm_scale(
    const float* __restrict__ xparam, const float* __restrict__ W, int n)
{
    const float* in = xparam ? xparam : g_bufB;
    __shared__ float Ws[64 * 64];
    __shared__ float xsh[8][8 * 64];
    int t = threadIdx.x;
    const float4* W4 = (const float4*)W;
    float4* Ws4 = (float4*)Ws;
#pragma unroll
    for (int i = 0; i < 4; i++) Ws4[t + i * 256] = W4[t + i * 256];
    __syncthreads();

    int w = t >> 5, lane = t & 31;
    int rowBase = blockIdx.x * 64 + w * 8;
    if (rowBase >= n) return;
    int rows = min(8, n - rowBase);

    for (int idx = lane; idx < rows * 64; idx += 32)
        xsh[w][idx] = in[(size_t)rowBase * 64 + idx];
    __syncwarp();

    float acc0[8], acc1[8];
#pragma unroll
    for (int r = 0; r < 8; r++) { acc0[r] = 0.f; acc1[r] = 0.f; }

#pragma unroll 4
    for (int k = 0; k < 64; k++) {
        float w0 = Ws[k * 64 + lane];
        float w1 = Ws[k * 64 + lane + 32];
#pragma unroll
        for (int r = 0; r < 8; r++) {
            float a = xsh[w][r * 64 + k];
            acc0[r] = fmaf(a, w0, acc0[r]);
            acc1[r] = fmaf(a, w1, acc1[r]);
        }
    }

    for (int r = 0; r < rows; r++) {
        int row = rowBase + r;
        float sc = g_dinv[row];
        g_bufA[(size_t)row * 64 + lane]      = acc0[r] * sc;
        g_bufA[(size_t)row * 64 + lane + 32] = acc1[r] * sc;
    }
}

// one warp per dst node: g_bufB[d] = relu(dinv[d]*(A[d] + sum_{s in N(d)} A[s]) + b)
__global__ __launch_bounds__(256) void k_aggregate(
    const float* __restrict__ b, int n)
{
    int gw = (blockIdx.x * blockDim.x + threadIdx.x) >> 5;
    int lane = threadIdx.x & 31;
    if (gw >= n) return;
    int d = gw;

    const float2* xs2 = (const float2*)g_bufA;
    float2 acc = xs2[(size_t)d * 32 + lane];   // self-loop term (pre-scaled)

    int e  = g_rowptr[d];
    int e1 = g_rowptr[d + 1];
    for (; e + 4 <= e1; e += 4) {
        int i0 = g_colidx[e + 0];
        int i1 = g_colidx[e + 1];
        int i2 = g_colidx[e + 2];
        int i3 = g_colidx[e + 3];
        float2 v0 = xs2[(size_t)i0 * 32 + lane];
        float2 v1 = xs2[(size_t)i1 * 32 + lane];
        float2 v2 = xs2[(size_t)i2 * 32 + lane];
        float2 v3 = xs2[(size_t)i3 * 32 + lane];
        acc.x += v0.x + v1.x + v2.x + v3.x;
        acc.y += v0.y + v1.y + v2.y + v3.y;
    }
    for (; e < e1; e++) {
        int s = g_colidx[e];
        float2 v = xs2[(size_t)s * 32 + lane];
        acc.x += v.x; acc.y += v.y;
    }

    float sc = g_dinv[d];
    float2 bb = ((const float2*)b)[lane];
    float2 o;
    o.x = fmaxf(fmaf(acc.x, sc, bb.x), 0.f);
    o.y = fmaxf(fmaf(acc.y, sc, bb.y), 0.f);
    ((float2*)g_bufB)[(size_t)d * 32 + lane] = o;
}

// mean-pool partial sums over g_bufB: grid (G, 8), block 256
__global__ void k_pool(int n)
{
    __shared__ int sLo, sHi;
    __shared__ float part[4][64];
    int g = blockIdx.x;
    int t = threadIdx.x;
    if (t == 0) {
        sLo = lower_bound_i(g_bat, n, g);
        sHi = lower_bound_i(g_bat, n, g + 1);
    }
    __syncthreads();
    int lo = sLo, hi = sHi;
    int col = t & 63, q = t >> 6;
    float acc = 0.f;
    for (int r = lo + (int)blockIdx.y * 4 + q; r < hi; r += 32)
        acc += g_bufB[(size_t)r * 64 + col];
    part[q][col] = acc;
    __syncthreads();
    if (t < 64) {
        float s = part[0][t] + part[1][t] + part[2][t] + part[3][t];
        atomicAdd(&g_pooled[g * 64 + t], s);
    }
}

// head: pooled/cnt @ Wfc + bfc -> log_softmax
__global__ void k_head(const float* __restrict__ Wfc,
                       const float* __restrict__ bfc,
                       float* __restrict__ out, int n)
{
    int g = threadIdx.x;
    if (g >= GG) return;
    int lo = lower_bound_i(g_bat, n, g);
    int hi = lower_bound_i(g_bat, n, g + 1);
    float inv = 1.0f / (float)max(hi - lo, 1);
    float l0 = bfc[0], l1 = bfc[1];
    for (int j = 0; j < 64; j++) {
        float p = g_pooled[g * 64 + j] * inv;
        l0 = fmaf(p, Wfc[2 * j + 0], l0);
        l1 = fmaf(p, Wfc[2 * j + 1], l1);
    }
    float m = fmaxf(l0, l1);
    float lse = m + logf(expf(l0 - m) + expf(l1 - m));
    out[2 * g + 0] = l0 - lse;
    out[2 * g + 1] = l1 - lse;
}

// ---------------- launch -----------------------------------------------------
extern "C" void kernel_launch(void* const* d_in, const int* in_sizes, int n_in,
                              void* d_out, int out_size) {
    const float* x   = (const float*)d_in[0];
    const void*  ei  = d_in[1];
    const void*  bat = d_in[2];
    const float* W1  = (const float*)d_in[3];
    const float* b1  = (const float*)d_in[4];
    const float* W2  = (const float*)d_in[5];
    const float* b2  = (const float*)d_in[6];
    const float* Wfc = (const float*)d_in[7];
    const float* bfc = (const float*)d_in[8];
    float* out = (float*)d_out;

    int n = in_sizes[0] / DD;      // 100000
    int e = in_sizes[1] / 2;       // 1600000
    int nb = (n + 1023) / 1024;    // scan blocks

    // dtype detect + conversion + CSR build
    k_detect<<<1, 256>>>(ei, e);
    k_zero<<<(n + 255) / 256, 256>>>(n);
    k_convert_edges<<<(e + 255) / 256, 256>>>(ei, e);
    k_convert_batch<<<(n + 255) / 256, 256>>>(bat, n);
    k_scan1<<<nb, 1024>>>(n);
    k_scan2<<<1, 128>>>(nb);
    k_scan3<<<(n + 255) / 256, 256>>>(n, e);
    k_fill<<<(e + 255) / 256, 256>>>(e);

    int gemm_grid = (n + 63) / 64;
    int agg_grid  = (n * 32 + 255) / 256;

    // layer 1
    k_gemm_scale<<<gemm_grid, 256>>>(x, W1, n);
    k_aggregate<<<agg_grid, 256>>>(b1, n);
    // layer 2
    k_gemm_scale<<<gemm_grid, 256>>>(nullptr, W2, n);
    k_aggregate<<<agg_grid, 256>>>(b2, n);

    // pool + head
    k_pool<<<dim3(GG, 8), 256>>>(n);
    k_head<<<1, 64>>>(Wfc, bfc, out, n);
}